// round 6
// baseline (speedup 1.0000x reference)
#include <cuda_runtime.h>
#include <cuda_bf16.h>
#include <math.h>
#include <stdint.h>

// Problem dims
#define N_TOK 32768
#define L_SEQ 512
#define B_ROWS 64
#define HDIM 768
#define EDIM 1000
#define PDIM 300

// ---------------- scratch ----------------
__device__ float g_means[(size_t)N_TOK * HDIM];
__device__ float g_h1[(size_t)N_TOK * HDIM];
__device__ float g_P[EDIM * PDIM];
__device__ float g_w1t[HDIM * HDIM];
__device__ float g_wdT[PDIM * HDIM];
__device__ float g_Qt[1024 * HDIM];              // rows 1000..1023 stay zero (never written)
__device__ int   g_pred[N_TOK];
__device__ int   g_nzTok[N_TOK];
__device__ int   g_cumB[N_TOK];
__device__ int   g_segStart[N_TOK];
__device__ int   g_outRow[N_TOK];
__device__ int   g_c[2][B_ROWS];
__device__ int   g_hdr[3];
__device__ int   g_fixCount;
__device__ int   g_fixList[N_TOK];

// ======================= dtype helpers =======================
__device__ __forceinline__ void split_bf16_pair(float x, float y, uint32_t& hi, uint32_t& lo) {
    __nv_bfloat162 h2 = __float22bfloat162_rn(make_float2(x, y));
    uint32_t hb = *reinterpret_cast<uint32_t*>(&h2);       // low16=bf16(x), high16=bf16(y)
    float hx = __uint_as_float(hb << 16);
    float hy = __uint_as_float(hb & 0xffff0000u);
    __nv_bfloat162 l2 = __float22bfloat162_rn(make_float2(x - hx, y - hy));
    hi = hb;
    lo = *reinterpret_cast<uint32_t*>(&l2);
}

#define MMA_BF16(d, a, b) \
    asm volatile("mma.sync.aligned.m16n8k16.row.col.f32.bf16.bf16.f32 " \
        "{%0,%1,%2,%3}, {%4,%5,%6,%7}, {%8,%9}, {%0,%1,%2,%3};" \
        : "+f"((d)[0]), "+f"((d)[1]), "+f"((d)[2]), "+f"((d)[3]) \
        : "r"((a)[0]), "r"((a)[1]), "r"((a)[2]), "r"((a)[3]), "r"((b)[0]), "r"((b)[1]))

// SMEM stride (uint32 units): 16 packed bf16x2 + pad 4
#define TLD16 20
#define STAGE_U32 (4 * 128 * TLD16)
#define SMEM_BF16 (2 * STAGE_U32 * 4)   // 81920 B

// ======================= global -> register tile prefetch =======================
__device__ __forceinline__ void ldg_tile(
    const float* __restrict__ src, int rbase, int rmax, int ld, int K, int kbase,
    float4* p, int tid)
{
#pragma unroll
    for (int i = 0; i < 4; i++) {
        int idx = i * 256 + tid;
        int r = idx >> 3, q = idx & 7;
        int gr = rbase + r, gk = kbase + q * 4;
        float4 v = make_float4(0.f, 0.f, 0.f, 0.f);
        if (gr < rmax && gk + 4 <= K)
            v = *reinterpret_cast<const float4*>(src + (size_t)gr * ld + gk);
        p[i] = v;
    }
}

__device__ __forceinline__ void sts_tile(uint32_t* st, const float4* pa, const float4* pb, int tid)
{
    uint32_t* Ah = st;
    uint32_t* Al = st + 128 * TLD16;
    uint32_t* Bh = st + 2 * 128 * TLD16;
    uint32_t* Bl = st + 3 * 128 * TLD16;
#pragma unroll
    for (int i = 0; i < 4; i++) {
        int idx = i * 256 + tid;
        int off = (idx >> 3) * TLD16 + (idx & 7) * 2;
        float4 va = pa[i], vb = pb[i];
        uint32_t h0, l0, h1, l1;
        split_bf16_pair(va.x, va.y, h0, l0);
        split_bf16_pair(va.z, va.w, h1, l1);
        *reinterpret_cast<uint2*>(Ah + off) = make_uint2(h0, h1);
        *reinterpret_cast<uint2*>(Al + off) = make_uint2(l0, l1);
        split_bf16_pair(vb.x, vb.y, h0, l0);
        split_bf16_pair(vb.z, vb.w, h1, l1);
        *reinterpret_cast<uint2*>(Bh + off) = make_uint2(h0, h1);
        *reinterpret_cast<uint2*>(Bl + off) = make_uint2(l0, l1);
    }
}

__device__ __forceinline__ void compute_tile(
    const uint32_t* st, float acc[2][8][4], int wm, int wn, int g, int t4)
{
    const uint32_t* AH = st;
    const uint32_t* AL = st + 128 * TLD16;
    const uint32_t* BH = st + 2 * 128 * TLD16;
    const uint32_t* BL = st + 3 * 128 * TLD16;
#pragma unroll
    for (int kh = 0; kh < 2; kh++) {
        const int kb = kh * 8;
        uint32_t ah[2][4], al[2][4];
#pragma unroll
        for (int mt = 0; mt < 2; mt++) {
            int R = (wm * 32 + mt * 16 + g) * TLD16 + kb + t4;
            ah[mt][0] = AH[R];              ah[mt][1] = AH[R + 8 * TLD16];
            ah[mt][2] = AH[R + 4];          ah[mt][3] = AH[R + 8 * TLD16 + 4];
            al[mt][0] = AL[R];              al[mt][1] = AL[R + 8 * TLD16];
            al[mt][2] = AL[R + 4];          al[mt][3] = AL[R + 8 * TLD16 + 4];
        }
        uint32_t bh[8][2], bl[8][2];
#pragma unroll
        for (int nt = 0; nt < 8; nt++) {
            int Cb = (wn * 64 + nt * 8 + g) * TLD16 + kb + t4;
            bh[nt][0] = BH[Cb]; bh[nt][1] = BH[Cb + 4];
            bl[nt][0] = BL[Cb]; bl[nt][1] = BL[Cb + 4];
        }
#pragma unroll
        for (int mt = 0; mt < 2; mt++)
#pragma unroll
            for (int nt = 0; nt < 8; nt++) MMA_BF16(acc[mt][nt], ah[mt], bh[nt]);
#pragma unroll
        for (int mt = 0; mt < 2; mt++)
#pragma unroll
            for (int nt = 0; nt < 8; nt++) MMA_BF16(acc[mt][nt], al[mt], bh[nt]);
#pragma unroll
        for (int mt = 0; mt < 2; mt++)
#pragma unroll
            for (int nt = 0; nt < 8; nt++) MMA_BF16(acc[mt][nt], ah[mt], bl[nt]);
    }
}

// ======================= pipelined 3-term split-bf16 GEMM =======================
// D[M,N] = A[M,K] @ B[NB,K]^T.  MODE: 0 plain, 1 bias+relu, 2 dyn-M + row remap.
template <int MODE>
__global__ __launch_bounds__(256, 1) void tc_gemm(
    const float* __restrict__ A, const float* __restrict__ Bm, float* __restrict__ Cm,
    const float* __restrict__ bias, int M, int N, int NB, int K, int lda, int ldb, int ldc)
{
    extern __shared__ uint32_t sm[];
    const int tid = threadIdx.x;
    const int wid = tid >> 5, lane = tid & 31;
    const int g = lane >> 2, t4 = lane & 3;
    const int wm = wid & 3, wn = wid >> 2;
    const int row0 = blockIdx.y * 128, col0 = blockIdx.x * 128;
    const int Meff = (MODE == 2) ? g_hdr[1] : M;
    if (row0 >= Meff) return;

    float acc[2][8][4];
#pragma unroll
    for (int mt = 0; mt < 2; mt++)
#pragma unroll
        for (int nt = 0; nt < 8; nt++)
#pragma unroll
            for (int c = 0; c < 4; c++) acc[mt][nt][c] = 0.f;

    const int KTILES = (K + 31) >> 5;
    float4 pa[4], pb[4];

    ldg_tile(A, row0, Meff, lda, K, 0, pa, tid);
    ldg_tile(Bm, col0, NB, ldb, K, 0, pb, tid);
    sts_tile(sm, pa, pb, tid);
    __syncthreads();

    for (int kt = 0; kt < KTILES; kt++) {
        const bool has_next = (kt + 1 < KTILES);
        if (has_next) {
            int kb = (kt + 1) << 5;
            ldg_tile(A, row0, Meff, lda, K, kb, pa, tid);
            ldg_tile(Bm, col0, NB, ldb, K, kb, pb, tid);
        }
        compute_tile(sm + (kt & 1) * STAGE_U32, acc, wm, wn, g, t4);
        if (has_next) {
            sts_tile(sm + ((kt + 1) & 1) * STAGE_U32, pa, pb, tid);
            __syncthreads();
        }
    }

    // epilogue
#pragma unroll
    for (int mt = 0; mt < 2; mt++) {
        int rA = row0 + wm * 32 + mt * 16 + g;
        int rB = rA + 8;
        bool vA = rA < Meff, vB = rB < Meff;
        int oA = 0, oB = 0;
        if (MODE == 2) {
            if (vA) oA = g_outRow[rA];
            if (vB) oB = g_outRow[rB];
        } else { oA = rA; oB = rB; }
#pragma unroll
        for (int nt = 0; nt < 8; nt++) {
            int c0 = col0 + wn * 64 + nt * 8 + 2 * t4;
            int c1 = c0 + 1;
            float v0 = acc[mt][nt][0], v1 = acc[mt][nt][1];
            float v2 = acc[mt][nt][2], v3 = acc[mt][nt][3];
            if (MODE == 1) {
                float bb0 = (c0 < N) ? bias[c0] : 0.f;
                float bb1 = (c1 < N) ? bias[c1] : 0.f;
                v0 = fmaxf(v0 + bb0, 0.f); v1 = fmaxf(v1 + bb1, 0.f);
                v2 = fmaxf(v2 + bb0, 0.f); v3 = fmaxf(v3 + bb1, 0.f);
            }
            if (vA) {
                if (c0 < N) Cm[(size_t)oA * ldc + c0] = v0;
                if (c1 < N) Cm[(size_t)oA * ldc + c1] = v1;
            }
            if (vB) {
                if (c0 < N) Cm[(size_t)oB * ldc + c0] = v2;
                if (c1 < N) Cm[(size_t)oB * ldc + c1] = v3;
            }
        }
    }
}

// ======================= second MLP layer + log-softmax + argmax + ambiguity flag ===========
#define GAP_THRESH 5e-4f
__global__ __launch_bounds__(256) void mlp2_kernel(
    const float* __restrict__ h1, const float* __restrict__ w2,
    const float* __restrict__ b2, float* __restrict__ out_logits)
{
    __shared__ float w2s[HDIM * 3];
    for (int i = threadIdx.x; i < HDIM * 3; i += 256) w2s[i] = w2[i];
    __syncthreads();
    int warp = threadIdx.x >> 5, lid = threadIdx.x & 31;
    int row = blockIdx.x * 8 + warp;
    const float* hr = h1 + (size_t)row * HDIM;
    float a0 = 0.f, a1 = 0.f, a2 = 0.f;
    for (int k = lid; k < HDIM; k += 32) {
        float h = hr[k];
        a0 += h * w2s[k * 3 + 0];
        a1 += h * w2s[k * 3 + 1];
        a2 += h * w2s[k * 3 + 2];
    }
#pragma unroll
    for (int s = 16; s > 0; s >>= 1) {
        a0 += __shfl_down_sync(0xffffffffu, a0, s);
        a1 += __shfl_down_sync(0xffffffffu, a1, s);
        a2 += __shfl_down_sync(0xffffffffu, a2, s);
    }
    if (lid == 0) {
        float l0 = a0 + b2[0], l1 = a1 + b2[1], l2 = a2 + b2[2];
        float m = fmaxf(l0, fmaxf(l1, l2));
        float lse = m + __logf(__expf(l0 - m) + __expf(l1 - m) + __expf(l2 - m));
        out_logits[(size_t)row * 3 + 0] = l0 - lse;
        out_logits[(size_t)row * 3 + 1] = l1 - lse;
        out_logits[(size_t)row * 3 + 2] = l2 - lse;
        int a = 0;
        if (l1 > l0) a = 1;
        float la = (a == 1) ? l1 : l0;
        if (l2 > la) a = 2;
        g_pred[row] = a;
        // top-2 gap: if ambiguous under bf16-3term error bound, queue exact recompute
        float top1 = fmaxf(l0, fmaxf(l1, l2));
        float top2 = -3.0e38f;
        if (l0 < top1 || (a != 0)) top2 = fmaxf(top2, l0);
        if (l1 < top1 || (a != 1)) top2 = fmaxf(top2, l1);
        if (l2 < top1 || (a != 2)) top2 = fmaxf(top2, l2);
        if (top1 - top2 < GAP_THRESH) {
            int slot = atomicAdd(&g_fixCount, 1);
            if (slot < N_TOK) g_fixList[slot] = row;
        }
    }
}

// ======================= exact fp32 fixup for ambiguous rows =======================
__global__ __launch_bounds__(256) void fixup_kernel(
    const float* __restrict__ hidden, const float* __restrict__ w1t,
    const float* __restrict__ b1, const float* __restrict__ w2,
    const float* __restrict__ b2, float* __restrict__ out_logits)
{
    __shared__ float sh[HDIM];
    __shared__ float red0[256], red1[256], red2[256];
    const int tid = threadIdx.x;
    const int nfix = min(g_fixCount, N_TOK);
    for (int it = blockIdx.x; it < nfix; it += gridDim.x) {
        int row = g_fixList[it];
        const float* hr = hidden + (size_t)row * HDIM;
        for (int j = tid; j < HDIM; j += 256) sh[j] = hr[j];
        __syncthreads();
        float l0 = 0.f, l1 = 0.f, l2 = 0.f;
#pragma unroll
        for (int kk = 0; kk < 3; kk++) {
            int k = tid + kk * 256;
            const float* wc = w1t + (size_t)k * HDIM;
            float acc = b1[k];
            for (int j = 0; j < HDIM; j++) acc = fmaf(sh[j], wc[j], acc);
            float h = fmaxf(acc, 0.f);
            l0 += h * w2[k * 3 + 0];
            l1 += h * w2[k * 3 + 1];
            l2 += h * w2[k * 3 + 2];
        }
        red0[tid] = l0; red1[tid] = l1; red2[tid] = l2;
        __syncthreads();
        for (int s = 128; s > 0; s >>= 1) {
            if (tid < s) {
                red0[tid] += red0[tid + s];
                red1[tid] += red1[tid + s];
                red2[tid] += red2[tid + s];
            }
            __syncthreads();
        }
        if (tid == 0) {
            float f0 = red0[0] + b2[0], f1 = red1[0] + b2[1], f2 = red2[0] + b2[2];
            float m = fmaxf(f0, fmaxf(f1, f2));
            float lse = m + logf(expf(f0 - m) + expf(f1 - m) + expf(f2 - m));
            out_logits[(size_t)row * 3 + 0] = f0 - lse;
            out_logits[(size_t)row * 3 + 1] = f1 - lse;
            out_logits[(size_t)row * 3 + 2] = f2 - lse;
            int a = 0;
            if (f1 > f0) a = 1;
            float la = (a == 1) ? f1 : f0;
            if (f2 > la) a = 2;
            g_pred[row] = a;
        }
        __syncthreads();
    }
}

// ======================= transpose =======================
__global__ void transpose_kernel(const float* __restrict__ P, float* __restrict__ Pt,
                                 int rows, int cols)
{
    __shared__ float s[32][33];
    int c0 = blockIdx.x * 32, r0 = blockIdx.y * 32;
    int tx = threadIdx.x, ty = threadIdx.y;
#pragma unroll
    for (int t = 0; t < 4; t++) {
        int r = r0 + ty + t * 8, c = c0 + tx;
        s[ty + t * 8][tx] = (r < rows && c < cols) ? P[(size_t)r * cols + c] : 0.f;
    }
    __syncthreads();
#pragma unroll
    for (int t = 0; t < 4; t++) {
        int r = c0 + ty + t * 8, c = r0 + tx;
        if (r < cols && c < rows) Pt[(size_t)r * rows + c] = s[tx][ty + t * 8];
    }
}

// ======================= scan kernel (1 block) =======================
__global__ void scan_kernel(const int* __restrict__ labels_in, int setIdx, int usePred)
{
    __shared__ int sNZ[1024], sB[1024];
    __shared__ int s_idx0;
    __shared__ int sC[B_ROWS], sSt[B_ROWS];
    const int* lab = usePred ? (const int*)g_pred : labels_in;
    const int tid = threadIdx.x;
    const int IPT = N_TOK / 1024;
    const int base = tid * IPT;

    int cn = 0, cb = 0;
    for (int t = 0; t < IPT; t++) {
        int l = lab[base + t];
        cn += (l != 0);
        cb += (l == 1);
    }
    sNZ[tid] = cn; sB[tid] = cb;
    if (tid == 0) s_idx0 = N_TOK;
    __syncthreads();
    if (tid == 0) {
        int an = 0, ab = 0;
        for (int t = 0; t < 1024; t++) {
            int n = sNZ[t], b = sB[t];
            sNZ[t] = an; sB[t] = ab;
            an += n; ab += b;
        }
        g_hdr[0] = an;
        g_hdr[1] = ab;
    }
    __syncthreads();
    const int M = g_hdr[0], C = g_hdr[1];
    int pn = sNZ[tid], pb = sB[tid];
    for (int t = 0; t < IPT; t++) {
        int i = base + t;
        int l = lab[i];
        if (l != 0) {
            if (l == 1) { pb++; atomicMin(&s_idx0, pn); }
            g_nzTok[pn] = i;
            g_cumB[pn] = pb;
            pn++;
        }
    }
    __syncthreads();
    const int idx0 = (C > 0) ? s_idx0 : 0;
    if (tid == 0) g_hdr[2] = idx0;
    if (C > 0) {
        for (int p = tid; p < M; p += 1024) {
            int q = min(p + idx0, N_TOK - 1);
            int s = ((q < M) ? g_cumB[q] : C) - 1;
            if (p == 0) {
                g_segStart[0] = 0;
            } else {
                int q2 = min(p - 1 + idx0, N_TOK - 1);
                int s2 = ((q2 < M) ? g_cumB[q2] : C) - 1;
                if (s != s2) g_segStart[s] = p;
            }
        }
    }
    if (tid < B_ROWS) {
        int cnt = 0;
        for (int l = 0; l < L_SEQ; l++) cnt += (lab[tid * L_SEQ + l] == 1);
        sC[tid] = cnt;
    }
    __syncthreads();
    if (tid == 0) {
        int a = 0;
        for (int b = 0; b < B_ROWS; b++) { sSt[b] = a; a += sC[b]; }
    }
    __syncthreads();
    if (tid < B_ROWS) {
        g_c[setIdx][tid] = sC[tid];
        int st = sSt[tid];
        for (int j = 0; j < sC[tid]; j++) g_outRow[st + j] = tid * L_SEQ + j;
    }
}

// ======================= segment means =======================
__global__ void means_kernel(const float* __restrict__ hidden)
{
    const int C = g_hdr[1], M = g_hdr[0];
    const int tid = threadIdx.x;
    for (int s = blockIdx.x; s < C; s += gridDim.x) {
        int st = g_segStart[s];
        int en = (s + 1 < C) ? g_segStart[s + 1] : M;
        float a0 = 0.f, a1 = 0.f, a2 = 0.f;
        for (int p = st; p < en; p++) {
            const float* h = hidden + (size_t)g_nzTok[p] * HDIM;
            a0 += h[tid];
            a1 += h[tid + 256];
            a2 += h[tid + 512];
        }
        float inv = 1.f / (float)(en - st);
        float* m = g_means + (size_t)s * HDIM;
        m[tid] = a0 * inv;
        m[tid + 256] = a1 * inv;
        m[tid + 512] = a2 * inv;
    }
}

// ======================= row-wise log-softmax over E =======================
__global__ void softmax_kernel(float* __restrict__ scores)
{
    __shared__ float red[256];
    const int gid = blockIdx.x;
    const int set = gid >> 15;
    const int r = gid & (N_TOK - 1);
    const int b = r / L_SEQ, j = r - b * L_SEQ;
    float* row = scores + (size_t)set * N_TOK * EDIM + (size_t)r * EDIM;
    const int tid = threadIdx.x;
    const int NV = EDIM / 4;

    if (j >= g_c[set][b]) {
        const float c = -6.9077552789821368f;
        if (tid < NV) reinterpret_cast<float4*>(row)[tid] = make_float4(c, c, c, c);
        return;
    }
    float4 v = make_float4(0.f, 0.f, 0.f, 0.f);
    float m = -3.0e38f;
    if (tid < NV) {
        v = reinterpret_cast<const float4*>(row)[tid];
        m = fmaxf(fmaxf(v.x, v.y), fmaxf(v.z, v.w));
    }
    red[tid] = m;
    __syncthreads();
    for (int s = 128; s > 0; s >>= 1) {
        if (tid < s) red[tid] = fmaxf(red[tid], red[tid + s]);
        __syncthreads();
    }
    float vmax = red[0];
    __syncthreads();
    float se = 0.f;
    if (tid < NV)
        se = __expf(v.x - vmax) + __expf(v.y - vmax) + __expf(v.z - vmax) + __expf(v.w - vmax);
    red[tid] = se;
    __syncthreads();
    for (int s = 128; s > 0; s >>= 1) {
        if (tid < s) red[tid] += red[tid + s];
        __syncthreads();
    }
    float lse = vmax + __logf(red[0]);
    if (tid < NV) {
        v.x -= lse; v.y -= lse; v.z -= lse; v.w -= lse;
        reinterpret_cast<float4*>(row)[tid] = v;
    }
}

// ======================= launch =======================
extern "C" void kernel_launch(void* const* d_in, const int* in_sizes, int n_in,
                              void* d_out, int out_size)
{
    const int*   labels    = (const int*)d_in[0];
    const float* hidden    = (const float*)d_in[1];
    const float* ent       = (const float*)d_in[2];
    const float* w1        = (const float*)d_in[3];
    const float* b1        = (const float*)d_in[4];
    const float* w2        = (const float*)d_in[5];
    const float* b2        = (const float*)d_in[6];
    const float* w_mention = (const float*)d_in[7];
    const float* w_desc    = (const float*)d_in[8];
    float* out = (float*)d_out;

    cudaFuncSetAttribute(tc_gemm<0>, cudaFuncAttributeMaxDynamicSharedMemorySize, SMEM_BF16);
    cudaFuncSetAttribute(tc_gemm<1>, cudaFuncAttributeMaxDynamicSharedMemorySize, SMEM_BF16);
    cudaFuncSetAttribute(tc_gemm<2>, cudaFuncAttributeMaxDynamicSharedMemorySize, SMEM_BF16);

    void *pP, *pQt, *pMeans, *pH1, *pW1t, *pWdT, *pFix;
    cudaGetSymbolAddress(&pP, g_P);
    cudaGetSymbolAddress(&pQt, g_Qt);
    cudaGetSymbolAddress(&pMeans, g_means);
    cudaGetSymbolAddress(&pH1, g_h1);
    cudaGetSymbolAddress(&pW1t, g_w1t);
    cudaGetSymbolAddress(&pWdT, g_wdT);
    cudaGetSymbolAddress(&pFix, g_fixCount);

    cudaMemsetAsync(pFix, 0, sizeof(int));

    // transposes: w1t = w1^T [768x768], wdT = w_desc^T [300x768]
    transpose_kernel<<<dim3(24, 24), dim3(32, 8)>>>(w1, (float*)pW1t, HDIM, HDIM);
    transpose_kernel<<<dim3(10, 24), dim3(32, 8)>>>(w_desc, (float*)pWdT, HDIM, PDIM);

    // h1 = relu(hidden @ w1 + b1)  (bf16 3-term; ambiguous rows fixed later)
    tc_gemm<1><<<dim3(6, 256), 256, SMEM_BF16>>>(
        hidden, (const float*)pW1t, (float*)pH1, b1,
        N_TOK, HDIM, HDIM, HDIM, HDIM, HDIM, HDIM);

    // logits + argmax + ambiguity list
    mlp2_kernel<<<N_TOK / 8, 256>>>((const float*)pH1, w2, b2, out);

    // exact fp32 recompute of ambiguous rows
    fixup_kernel<<<128, 256>>>(hidden, (const float*)pW1t, b1, w2, b2, out);

    // P = ent @ w_desc   [1000 x 300]
    tc_gemm<0><<<dim3(3, 8), 256, SMEM_BF16>>>(
        ent, (const float*)pWdT, (float*)pP, nullptr,
        EDIM, PDIM, PDIM, HDIM, HDIM, HDIM, PDIM);

    // Qt = P @ w_mention^T   [1000 x 768]
    tc_gemm<0><<<dim3(6, 8), 256, SMEM_BF16>>>(
        (const float*)pP, w_mention, (float*)pQt, nullptr,
        EDIM, HDIM, HDIM, PDIM, PDIM, PDIM, HDIM);

    float* score_base = out + (size_t)N_TOK * 3;

    for (int set = 0; set < 2; set++) {
        scan_kernel<<<1, 1024>>>(labels, set, set);
        means_kernel<<<4096, 256>>>(hidden);
        tc_gemm<2><<<dim3(8, 256), 256, SMEM_BF16>>>(
            (const float*)pMeans, (const float*)pQt,
            score_base + (size_t)set * N_TOK * EDIM, nullptr,
            N_TOK, EDIM, 1024, HDIM, HDIM, HDIM, EDIM);
    }

    softmax_kernel<<<2 * N_TOK, 256>>>(score_base);
}